// round 14
// baseline (speedup 1.0000x reference)
#include <cuda_runtime.h>
#include <cuda_bf16.h>
#include <cstdint>

#define NN 100000
#define NE 1200000
#define FEAT4 16           // 64 floats = 16 float4 per node
#define NCLS 40
#define SCAN_NB 391        // ceil(100000/256)

// ---------------- device scratch (no allocs allowed) ----------------
__device__ int    g_src[NE];
__device__ int    g_dst[NE];
__device__ int    g_cnt[NN];
__device__ int    g_rowptr[NN + 1];
__device__ int    g_fill[NN];
__device__ int    g_bsum[512];
__device__ float  g_dinv[NN];
__device__ int2   g_csr[NE];          // {src, bitcast(weight)} grouped by dst
__device__ float4 g_hop1[NN * FEAT4];
__device__ float4 g_hop2[NN * FEAT4];
__device__ float4 g_hop3[NN * FEAT4];
__device__ float4 g_h1[NN * FEAT4];
__device__ float4 g_h2[NN * FEAT4];
__device__ int    g_is64;

// ---------------- dtype detection (int64 vs int32 edge_index) -------
__global__ void k_detect(const long long* p) {
    if (blockIdx.x == 0 && threadIdx.x == 0) {
        int ok = 1;
        #pragma unroll 1
        for (int i = 0; i < 64; i++) {
            long long v = p[i * 997];
            if (v < 0 || v >= NN) { ok = 0; break; }
        }
        g_is64 = ok;
    }
}

// ---------------- convert + degree histogram fused ------------------
__global__ void k_convert_hist(const void* edges) {
    int e = blockIdx.x * blockDim.x + threadIdx.x;
    if (e >= NE) return;
    int s, d;
    if (g_is64) {
        const long long* p = (const long long*)edges;
        s = (int)p[e];
        d = (int)p[e + NE];
    } else {
        const int* p = (const int*)edges;
        s = p[e];
        d = p[e + NE];
    }
    g_src[e] = s;
    g_dst[e] = d;
    atomicAdd(&g_cnt[d], 1);
}

__global__ void k_dinv() {
    int n = blockIdx.x * blockDim.x + threadIdx.x;
    if (n < NN) {
        float d = (float)g_cnt[n];
        g_dinv[n] = (d > 0.f) ? rsqrtf(fmaxf(d, 1.f)) : 0.f;
    }
}

// ---------------- exclusive scan of g_cnt -> g_rowptr ---------------
__global__ void k_scan1() {
    __shared__ int sh[2][256];
    int tid = threadIdx.x;
    int gid = blockIdx.x * 256 + tid;
    int v = (gid < NN) ? g_cnt[gid] : 0;
    sh[0][tid] = v;
    __syncthreads();
    int cur = 0;
    #pragma unroll
    for (int off = 1; off < 256; off <<= 1) {
        int a = sh[cur][tid];
        if (tid >= off) a += sh[cur][tid - off];
        sh[cur ^ 1][tid] = a;
        cur ^= 1;
        __syncthreads();
    }
    int incl = sh[cur][tid];
    if (gid <= NN) g_rowptr[gid] = incl - v;
    if (tid == 255) g_bsum[blockIdx.x] = incl;
}

__global__ void k_scan2() {
    __shared__ int sh[2][512];
    int tid = threadIdx.x;
    int v = (tid < SCAN_NB) ? g_bsum[tid] : 0;
    sh[0][tid] = v;
    __syncthreads();
    int cur = 0;
    #pragma unroll
    for (int off = 1; off < 512; off <<= 1) {
        int a = sh[cur][tid];
        if (tid >= off) a += sh[cur][tid - off];
        sh[cur ^ 1][tid] = a;
        cur ^= 1;
        __syncthreads();
    }
    if (tid < SCAN_NB) g_bsum[tid] = sh[cur][tid] - v;
}

__global__ void k_scan3() {
    int gid = blockIdx.x * 256 + threadIdx.x;
    if (gid < NN) g_rowptr[gid] += g_bsum[gid >> 8];
    if (gid == 0) g_rowptr[NN] = NE;
}

// ---------------- CSR fill (weight fused) ---------------------------
__global__ void k_fill() {
    int e = blockIdx.x * blockDim.x + threadIdx.x;
    if (e >= NE) return;
    int s = g_src[e];
    int d = g_dst[e];
    int pos = g_rowptr[d] + atomicAdd(&g_fill[d], 1);
    float w = g_dinv[s] * g_dinv[d];
    g_csr[pos] = make_int2(s, __float_as_int(w));
}

// ---------------- SpMM: warp per node, 2 edge-slots x 16 q-lanes ----
// Each slot unrolls by 2 -> 4 independent gather chains in flight/warp.
__global__ void __launch_bounds__(256) k_spmm_warp(
    const float4* __restrict__ feat, float4* __restrict__ out)
{
    int gw = (blockIdx.x * blockDim.x + threadIdx.x) >> 5;
    if (gw >= NN) return;
    int lane = threadIdx.x & 31;
    int half = lane >> 4;          // edge slot 0/1
    int q    = lane & 15;          // float4 index within row

    int beg = g_rowptr[gw];
    int end = g_rowptr[gw + 1];

    float4 acc = make_float4(0.f, 0.f, 0.f, 0.f);
    int i = beg + half;
    // unrolled: 2 edges per slot-iteration (stride 2 within slot)
    for (; i + 2 < end; i += 4) {
        int2 s0 = __ldg(&g_csr[i]);
        int2 s1 = __ldg(&g_csr[i + 2]);
        float4 v0 = __ldg(&feat[s0.x * FEAT4 + q]);
        float4 v1 = __ldg(&feat[s1.x * FEAT4 + q]);
        float w0 = __int_as_float(s0.y);
        float w1 = __int_as_float(s1.y);
        acc.x += w0 * v0.x + w1 * v1.x;
        acc.y += w0 * v0.y + w1 * v1.y;
        acc.z += w0 * v0.z + w1 * v1.z;
        acc.w += w0 * v0.w + w1 * v1.w;
    }
    if (i < end) {
        int2 s0 = __ldg(&g_csr[i]);
        float4 v0 = __ldg(&feat[s0.x * FEAT4 + q]);
        float w0 = __int_as_float(s0.y);
        acc.x += w0 * v0.x; acc.y += w0 * v0.y;
        acc.z += w0 * v0.z; acc.w += w0 * v0.w;
    }

    // combine the two edge slots (lane <- lane+16)
    acc.x += __shfl_down_sync(0xffffffffu, acc.x, 16);
    acc.y += __shfl_down_sync(0xffffffffu, acc.y, 16);
    acc.z += __shfl_down_sync(0xffffffffu, acc.z, 16);
    acc.w += __shfl_down_sync(0xffffffffu, acc.w, 16);

    if (half == 0) out[gw * FEAT4 + q] = acc;
}

// ====================================================================
// HMMA bf16 split-2 GEMM: out[128-tile,64] = concat(hops)[*,256] @ W + b
// ====================================================================
#define APITCH 72                    // bf16 elems per A row
#define A_SZ   (128 * APITCH)        // 9216 bf16
#define W_SZ   (64 * APITCH)         // 4608 bf16
#define OFF_ALO A_SZ
#define OFF_WHI (2 * A_SZ)
#define OFF_WLO (2 * A_SZ + W_SZ)
#define GEMM_SMEM ((2 * A_SZ + 2 * W_SZ) * 2)   // 55296 bytes -> 4 CTAs/SM

__device__ __forceinline__ void bsplit(float x, __nv_bfloat16& h, __nv_bfloat16& l) {
    h = __float2bfloat16(x);
    l = __float2bfloat16(x - __bfloat162float(h));
}

__device__ __forceinline__ void mma_bf16(float* c, const uint32_t* a,
                                         uint32_t b0, uint32_t b1) {
    asm volatile(
        "mma.sync.aligned.m16n8k16.row.col.f32.bf16.bf16.f32 "
        "{%0,%1,%2,%3}, {%4,%5,%6,%7}, {%8,%9}, {%0,%1,%2,%3};"
        : "+f"(c[0]), "+f"(c[1]), "+f"(c[2]), "+f"(c[3])
        : "r"(a[0]), "r"(a[1]), "r"(a[2]), "r"(a[3]), "r"(b0), "r"(b1));
}

__global__ void __launch_bounds__(128) k_gemm_mma(
    const float4* __restrict__ A0, const float4* __restrict__ A1,
    const float4* __restrict__ A2, const float4* __restrict__ A3,
    const float* __restrict__ W, const float* __restrict__ b,
    float* __restrict__ out, int relu)
{
    extern __shared__ __nv_bfloat16 shb[];
    __nv_bfloat16* Ahi = shb;
    __nv_bfloat16* Alo = shb + OFF_ALO;
    __nv_bfloat16* Whi = shb + OFF_WHI;
    __nv_bfloat16* Wlo = shb + OFF_WLO;
    const uint32_t* A32h = (const uint32_t*)Ahi;
    const uint32_t* A32l = (const uint32_t*)Alo;
    const uint32_t* W32h = (const uint32_t*)Whi;
    const uint32_t* W32l = (const uint32_t*)Wlo;

    const int tid  = threadIdx.x;
    const int lane = tid & 31;
    const int w    = tid >> 5;
    const int g    = lane >> 2;
    const int tig  = lane & 3;
    const int nb   = blockIdx.x * 128;

    float acc[2][8][4];
    #pragma unroll
    for (int mt = 0; mt < 2; mt++)
        #pragma unroll
        for (int nt = 0; nt < 8; nt++)
            #pragma unroll
            for (int i = 0; i < 4; i++) acc[mt][nt][i] = 0.f;

    #pragma unroll 1
    for (int c = 0; c < 4; c++) {
        const float4* Ap = (c == 0) ? A0 : (c == 1) ? A1 : (c == 2) ? A2 : A3;
        if (c) __syncthreads();

        {
            int node = nb + tid;
            const float4* row = Ap + (size_t)node * FEAT4;
            #pragma unroll
            for (int j = 0; j < 16; j++) {
                float4 v = (node < NN) ? __ldg(&row[j]) : make_float4(0, 0, 0, 0);
                __nv_bfloat16 h0, h1, h2, h3, l0, l1, l2, l3;
                bsplit(v.x, h0, l0); bsplit(v.y, h1, l1);
                bsplit(v.z, h2, l2); bsplit(v.w, h3, l3);
                int base = tid * APITCH + j * 4;
                *(__nv_bfloat162*)(Ahi + base)     = __nv_bfloat162(h0, h1);
                *(__nv_bfloat162*)(Ahi + base + 2) = __nv_bfloat162(h2, h3);
                *(__nv_bfloat162*)(Alo + base)     = __nv_bfloat162(l0, l1);
                *(__nv_bfloat162*)(Alo + base + 2) = __nv_bfloat162(l2, l3);
            }
        }
        {
            int n    = tid & 63;
            int half = tid >> 6;
            #pragma unroll
            for (int jj = 0; jj < 8; jj++) {
                int k0 = half * 32 + jj * 4;
                float w0 = __ldg(&W[(c * 64 + k0 + 0) * 64 + n]);
                float w1 = __ldg(&W[(c * 64 + k0 + 1) * 64 + n]);
                float w2 = __ldg(&W[(c * 64 + k0 + 2) * 64 + n]);
                float w3 = __ldg(&W[(c * 64 + k0 + 3) * 64 + n]);
                __nv_bfloat16 h0, h1, h2, h3, l0, l1, l2, l3;
                bsplit(w0, h0, l0); bsplit(w1, h1, l1);
                bsplit(w2, h2, l2); bsplit(w3, h3, l3);
                int base = n * APITCH + k0;
                *(__nv_bfloat162*)(Whi + base)     = __nv_bfloat162(h0, h1);
                *(__nv_bfloat162*)(Whi + base + 2) = __nv_bfloat162(h2, h3);
                *(__nv_bfloat162*)(Wlo + base)     = __nv_bfloat162(l0, l1);
                *(__nv_bfloat162*)(Wlo + base + 2) = __nv_bfloat162(l2, l3);
            }
        }
        __syncthreads();

        #pragma unroll
        for (int ks = 0; ks < 4; ks++) {
            int kw = ks * 8 + tig;
            uint32_t ahi[2][4], alo[2][4];
            #pragma unroll
            for (int mt = 0; mt < 2; mt++) {
                int r0 = (w * 32 + mt * 16 + g) * (APITCH / 2) + kw;
                int r1 = r0 + 8 * (APITCH / 2);
                ahi[mt][0] = A32h[r0]; ahi[mt][1] = A32h[r1];
                ahi[mt][2] = A32h[r0 + 4]; ahi[mt][3] = A32h[r1 + 4];
                alo[mt][0] = A32l[r0]; alo[mt][1] = A32l[r1];
                alo[mt][2] = A32l[r0 + 4]; alo[mt][3] = A32l[r1 + 4];
            }
            #pragma unroll
            for (int nt = 0; nt < 8; nt++) {
                int bw = (nt * 8 + g) * (APITCH / 2) + kw;
                uint32_t bh0 = W32h[bw], bh1 = W32h[bw + 4];
                uint32_t bl0 = W32l[bw], bl1 = W32l[bw + 4];
                #pragma unroll
                for (int mt = 0; mt < 2; mt++) {
                    mma_bf16(acc[mt][nt], ahi[mt], bh0, bh1);
                    mma_bf16(acc[mt][nt], ahi[mt], bl0, bl1);
                    mma_bf16(acc[mt][nt], alo[mt], bh0, bh1);
                }
            }
        }
    }

    #pragma unroll
    for (int mt = 0; mt < 2; mt++) {
        int row0 = nb + w * 32 + mt * 16 + g;
        int row1 = row0 + 8;
        #pragma unroll
        for (int nt = 0; nt < 8; nt++) {
            int col = nt * 8 + 2 * tig;
            float b0 = __ldg(&b[col]), b1 = __ldg(&b[col + 1]);
            float v0 = acc[mt][nt][0] + b0, v1 = acc[mt][nt][1] + b1;
            float v2 = acc[mt][nt][2] + b0, v3 = acc[mt][nt][3] + b1;
            if (relu) {
                v0 = fmaxf(v0, 0.f); v1 = fmaxf(v1, 0.f);
                v2 = fmaxf(v2, 0.f); v3 = fmaxf(v3, 0.f);
            }
            if (row0 < NN) *(float2*)(out + (size_t)row0 * 64 + col) = make_float2(v0, v1);
            if (row1 < NN) *(float2*)(out + (size_t)row1 * 64 + col) = make_float2(v2, v3);
        }
    }
}

// ---------------- classifier: [N,64] @ Wc[64,40] + bc ---------------
__global__ void k_classifier(const float* __restrict__ h,
                             const float* __restrict__ Wc,
                             const float* __restrict__ bc,
                             float* __restrict__ out)
{
    __shared__ float Ws[64 * NCLS];
    __shared__ float bs[NCLS];
    for (int i = threadIdx.x; i < 64 * NCLS; i += blockDim.x) Ws[i] = Wc[i];
    for (int i = threadIdx.x; i < NCLS; i += blockDim.x) bs[i] = bc[i];
    __syncthreads();

    int gid = blockIdx.x * blockDim.x + threadIdx.x;
    if (gid >= NN * NCLS) return;
    int n = gid / NCLS;
    int c = gid % NCLS;
    const float* row = h + (size_t)n * 64;
    float acc = bs[c];
    #pragma unroll
    for (int i = 0; i < 64; i++) acc += row[i] * Ws[i * NCLS + c];
    out[gid] = acc;
}

// ---------------- launch ---------------------------------------------
extern "C" void kernel_launch(void* const* d_in, const int* in_sizes, int n_in,
                              void* d_out, int out_size)
{
    const float* x  = (const float*)d_in[0];
    const void*  ei = d_in[1];
    const float* W1 = (const float*)d_in[2];
    const float* b1 = (const float*)d_in[3];
    const float* W2 = (const float*)d_in[4];
    const float* b2 = (const float*)d_in[5];
    const float* Wc = (const float*)d_in[6];
    const float* bc = (const float*)d_in[7];
    float* out = (float*)d_out;

    void* tmp;
    cudaGetSymbolAddress(&tmp, g_cnt);  int*    p_cnt  = (int*)tmp;
    cudaGetSymbolAddress(&tmp, g_fill); int*    p_fill = (int*)tmp;
    cudaGetSymbolAddress(&tmp, g_hop1); float4* p_hop1 = (float4*)tmp;
    cudaGetSymbolAddress(&tmp, g_hop2); float4* p_hop2 = (float4*)tmp;
    cudaGetSymbolAddress(&tmp, g_hop3); float4* p_hop3 = (float4*)tmp;
    cudaGetSymbolAddress(&tmp, g_h1);   float4* p_h1   = (float4*)tmp;
    cudaGetSymbolAddress(&tmp, g_h2);   float4* p_h2   = (float4*)tmp;

    cudaFuncSetAttribute(k_gemm_mma, cudaFuncAttributeMaxDynamicSharedMemorySize,
                         GEMM_SMEM);

    const int EB = (NE + 255) / 256;
    const int SB = (NN * 32 + 255) / 256;   // warp per node
    const int NB = (NN + 255) / 256;
    const int GB = (NN + 127) / 128;
    const int CB = (NN * NCLS + 255) / 256;

    // ---- CSR build ----
    k_detect<<<1, 32>>>((const long long*)ei);
    cudaMemsetAsync(p_cnt, 0, NN * sizeof(int));
    cudaMemsetAsync(p_fill, 0, NN * sizeof(int));
    k_convert_hist<<<EB, 256>>>(ei);
    k_dinv<<<NB, 256>>>();
    k_scan1<<<SCAN_NB, 256>>>();
    k_scan2<<<1, 512>>>();
    k_scan3<<<SCAN_NB, 256>>>();
    k_fill<<<EB, 256>>>();

    // ---- layer 1 ----
    k_spmm_warp<<<SB, 256>>>((const float4*)x, p_hop1);
    k_spmm_warp<<<SB, 256>>>(p_hop1, p_hop2);
    k_spmm_warp<<<SB, 256>>>(p_hop2, p_hop3);
    k_gemm_mma<<<GB, 128, GEMM_SMEM>>>((const float4*)x, p_hop1, p_hop2, p_hop3,
                                       W1, b1, (float*)p_h1, 1);

    // ---- layer 2 ----
    k_spmm_warp<<<SB, 256>>>(p_h1, p_hop1);
    k_spmm_warp<<<SB, 256>>>(p_hop1, p_hop2);
    k_spmm_warp<<<SB, 256>>>(p_hop2, p_hop3);
    k_gemm_mma<<<GB, 128, GEMM_SMEM>>>(p_h1, p_hop1, p_hop2, p_hop3,
                                       W2, b2, (float*)p_h2, 1);

    // ---- classifier ----
    k_classifier<<<CB, 256>>>((const float*)p_h2, Wc, bc, out);
}

// round 15
// speedup vs baseline: 1.4689x; 1.4689x over previous
#include <cuda_runtime.h>
#include <cuda_bf16.h>
#include <cstdint>

#define NN 100000
#define NE 1200000
#define FEAT4 16           // 64 floats = 16 float4 per node
#define NCLS 40
#define SCAN_NB 391        // ceil(100000/256)

// ---------------- device scratch (no allocs allowed) ----------------
__device__ int    g_src[NE];
__device__ int    g_dst[NE];
__device__ int    g_cnt[NN];
__device__ int    g_rowptr[NN + 1];
__device__ int    g_fill[NN];
__device__ int    g_bsum[512];
__device__ float  g_dinv[NN];
__device__ int2   g_csr[NE];          // {src, bitcast(weight)} grouped by dst
__device__ float4 g_hop1[NN * FEAT4];
__device__ float4 g_hop2[NN * FEAT4];
__device__ float4 g_hop3[NN * FEAT4];
__device__ float4 g_h1[NN * FEAT4];
__device__ float4 g_h2[NN * FEAT4];
__device__ int    g_is64;

// ---------------- dtype detection (int64 vs int32 edge_index) -------
__global__ void k_detect(const long long* p) {
    if (blockIdx.x == 0 && threadIdx.x == 0) {
        int ok = 1;
        #pragma unroll 1
        for (int i = 0; i < 64; i++) {
            long long v = p[i * 997];
            if (v < 0 || v >= NN) { ok = 0; break; }
        }
        g_is64 = ok;
    }
}

// ---------------- convert + degree histogram fused ------------------
__global__ void k_convert_hist(const void* edges) {
    int e = blockIdx.x * blockDim.x + threadIdx.x;
    if (e >= NE) return;
    int s, d;
    if (g_is64) {
        const long long* p = (const long long*)edges;
        s = (int)p[e];
        d = (int)p[e + NE];
    } else {
        const int* p = (const int*)edges;
        s = p[e];
        d = p[e + NE];
    }
    g_src[e] = s;
    g_dst[e] = d;
    atomicAdd(&g_cnt[d], 1);
}

__global__ void k_dinv() {
    int n = blockIdx.x * blockDim.x + threadIdx.x;
    if (n < NN) {
        float d = (float)g_cnt[n];
        g_dinv[n] = (d > 0.f) ? rsqrtf(fmaxf(d, 1.f)) : 0.f;
    }
}

// ---------------- exclusive scan of g_cnt -> g_rowptr ---------------
__global__ void k_scan1() {
    __shared__ int sh[2][256];
    int tid = threadIdx.x;
    int gid = blockIdx.x * 256 + tid;
    int v = (gid < NN) ? g_cnt[gid] : 0;
    sh[0][tid] = v;
    __syncthreads();
    int cur = 0;
    #pragma unroll
    for (int off = 1; off < 256; off <<= 1) {
        int a = sh[cur][tid];
        if (tid >= off) a += sh[cur][tid - off];
        sh[cur ^ 1][tid] = a;
        cur ^= 1;
        __syncthreads();
    }
    int incl = sh[cur][tid];
    if (gid <= NN) g_rowptr[gid] = incl - v;
    if (tid == 255) g_bsum[blockIdx.x] = incl;
}

__global__ void k_scan2() {
    __shared__ int sh[2][512];
    int tid = threadIdx.x;
    int v = (tid < SCAN_NB) ? g_bsum[tid] : 0;
    sh[0][tid] = v;
    __syncthreads();
    int cur = 0;
    #pragma unroll
    for (int off = 1; off < 512; off <<= 1) {
        int a = sh[cur][tid];
        if (tid >= off) a += sh[cur][tid - off];
        sh[cur ^ 1][tid] = a;
        cur ^= 1;
        __syncthreads();
    }
    if (tid < SCAN_NB) g_bsum[tid] = sh[cur][tid] - v;
}

__global__ void k_scan3() {
    int gid = blockIdx.x * 256 + threadIdx.x;
    if (gid < NN) g_rowptr[gid] += g_bsum[gid >> 8];
    if (gid == 0) g_rowptr[NN] = NE;
}

// ---------------- CSR fill (weight fused) ---------------------------
__global__ void k_fill() {
    int e = blockIdx.x * blockDim.x + threadIdx.x;
    if (e >= NE) return;
    int s = g_src[e];
    int d = g_dst[e];
    int pos = g_rowptr[d] + atomicAdd(&g_fill[d], 1);
    float w = g_dinv[s] * g_dinv[d];
    g_csr[pos] = make_int2(s, __float_as_int(w));
}

// ---------------- SpMM (CSR pull, 16 threads/node, unroll-4) --------
// Same mapping as the proven R10 kernel; only the inner loop is
// software-unrolled so 4 csr loads + 4 gathers are in flight at once.
__global__ void __launch_bounds__(256) k_spmm_csr(
    const float4* __restrict__ feat, float4* __restrict__ out)
{
    int gid = blockIdx.x * blockDim.x + threadIdx.x;
    if (gid >= NN * 16) return;
    int node = gid >> 4;
    int q    = gid & 15;
    int beg = g_rowptr[node];
    int end = g_rowptr[node + 1];
    float4 acc = make_float4(0.f, 0.f, 0.f, 0.f);

    int i = beg;
    for (; i + 4 <= end; i += 4) {
        int2 s0 = __ldg(&g_csr[i]);
        int2 s1 = __ldg(&g_csr[i + 1]);
        int2 s2 = __ldg(&g_csr[i + 2]);
        int2 s3 = __ldg(&g_csr[i + 3]);
        float4 v0 = __ldg(&feat[s0.x * FEAT4 + q]);
        float4 v1 = __ldg(&feat[s1.x * FEAT4 + q]);
        float4 v2 = __ldg(&feat[s2.x * FEAT4 + q]);
        float4 v3 = __ldg(&feat[s3.x * FEAT4 + q]);
        float w0 = __int_as_float(s0.y), w1 = __int_as_float(s1.y);
        float w2 = __int_as_float(s2.y), w3 = __int_as_float(s3.y);
        acc.x += w0 * v0.x + w1 * v1.x + w2 * v2.x + w3 * v3.x;
        acc.y += w0 * v0.y + w1 * v1.y + w2 * v2.y + w3 * v3.y;
        acc.z += w0 * v0.z + w1 * v1.z + w2 * v2.z + w3 * v3.z;
        acc.w += w0 * v0.w + w1 * v1.w + w2 * v2.w + w3 * v3.w;
    }
    for (; i < end; i++) {
        int2 sw = __ldg(&g_csr[i]);
        float w = __int_as_float(sw.y);
        float4 v = __ldg(&feat[sw.x * FEAT4 + q]);
        acc.x += w * v.x; acc.y += w * v.y;
        acc.z += w * v.z; acc.w += w * v.w;
    }
    out[node * FEAT4 + q] = acc;
}

// ====================================================================
// HMMA bf16 split-2 GEMM: out[128-tile,64] = concat(hops)[*,256] @ W + b
// ====================================================================
#define APITCH 72                    // bf16 elems per A row
#define A_SZ   (128 * APITCH)        // 9216 bf16
#define W_SZ   (64 * APITCH)         // 4608 bf16
#define OFF_ALO A_SZ
#define OFF_WHI (2 * A_SZ)
#define OFF_WLO (2 * A_SZ + W_SZ)
#define GEMM_SMEM ((2 * A_SZ + 2 * W_SZ) * 2)   // 55296 bytes -> 4 CTAs/SM

__device__ __forceinline__ void bsplit(float x, __nv_bfloat16& h, __nv_bfloat16& l) {
    h = __float2bfloat16(x);
    l = __float2bfloat16(x - __bfloat162float(h));
}

__device__ __forceinline__ void mma_bf16(float* c, const uint32_t* a,
                                         uint32_t b0, uint32_t b1) {
    asm volatile(
        "mma.sync.aligned.m16n8k16.row.col.f32.bf16.bf16.f32 "
        "{%0,%1,%2,%3}, {%4,%5,%6,%7}, {%8,%9}, {%0,%1,%2,%3};"
        : "+f"(c[0]), "+f"(c[1]), "+f"(c[2]), "+f"(c[3])
        : "r"(a[0]), "r"(a[1]), "r"(a[2]), "r"(a[3]), "r"(b0), "r"(b1));
}

__global__ void __launch_bounds__(128) k_gemm_mma(
    const float4* __restrict__ A0, const float4* __restrict__ A1,
    const float4* __restrict__ A2, const float4* __restrict__ A3,
    const float* __restrict__ W, const float* __restrict__ b,
    float* __restrict__ out, int relu)
{
    extern __shared__ __nv_bfloat16 shb[];
    __nv_bfloat16* Ahi = shb;
    __nv_bfloat16* Alo = shb + OFF_ALO;
    __nv_bfloat16* Whi = shb + OFF_WHI;
    __nv_bfloat16* Wlo = shb + OFF_WLO;
    const uint32_t* A32h = (const uint32_t*)Ahi;
    const uint32_t* A32l = (const uint32_t*)Alo;
    const uint32_t* W32h = (const uint32_t*)Whi;
    const uint32_t* W32l = (const uint32_t*)Wlo;

    const int tid  = threadIdx.x;
    const int lane = tid & 31;
    const int w    = tid >> 5;
    const int g    = lane >> 2;
    const int tig  = lane & 3;
    const int nb   = blockIdx.x * 128;

    float acc[2][8][4];
    #pragma unroll
    for (int mt = 0; mt < 2; mt++)
        #pragma unroll
        for (int nt = 0; nt < 8; nt++)
            #pragma unroll
            for (int i = 0; i < 4; i++) acc[mt][nt][i] = 0.f;

    #pragma unroll 1
    for (int c = 0; c < 4; c++) {
        const float4* Ap = (c == 0) ? A0 : (c == 1) ? A1 : (c == 2) ? A2 : A3;
        if (c) __syncthreads();

        {
            int node = nb + tid;
            const float4* row = Ap + (size_t)node * FEAT4;
            #pragma unroll
            for (int j = 0; j < 16; j++) {
                float4 v = (node < NN) ? __ldg(&row[j]) : make_float4(0, 0, 0, 0);
                __nv_bfloat16 h0, h1, h2, h3, l0, l1, l2, l3;
                bsplit(v.x, h0, l0); bsplit(v.y, h1, l1);
                bsplit(v.z, h2, l2); bsplit(v.w, h3, l3);
                int base = tid * APITCH + j * 4;
                *(__nv_bfloat162*)(Ahi + base)     = __nv_bfloat162(h0, h1);
                *(__nv_bfloat162*)(Ahi + base + 2) = __nv_bfloat162(h2, h3);
                *(__nv_bfloat162*)(Alo + base)     = __nv_bfloat162(l0, l1);
                *(__nv_bfloat162*)(Alo + base + 2) = __nv_bfloat162(l2, l3);
            }
        }
        {
            int n    = tid & 63;
            int half = tid >> 6;
            #pragma unroll
            for (int jj = 0; jj < 8; jj++) {
                int k0 = half * 32 + jj * 4;
                float w0 = __ldg(&W[(c * 64 + k0 + 0) * 64 + n]);
                float w1 = __ldg(&W[(c * 64 + k0 + 1) * 64 + n]);
                float w2 = __ldg(&W[(c * 64 + k0 + 2) * 64 + n]);
                float w3 = __ldg(&W[(c * 64 + k0 + 3) * 64 + n]);
                __nv_bfloat16 h0, h1, h2, h3, l0, l1, l2, l3;
                bsplit(w0, h0, l0); bsplit(w1, h1, l1);
                bsplit(w2, h2, l2); bsplit(w3, h3, l3);
                int base = n * APITCH + k0;
                *(__nv_bfloat162*)(Whi + base)     = __nv_bfloat162(h0, h1);
                *(__nv_bfloat162*)(Whi + base + 2) = __nv_bfloat162(h2, h3);
                *(__nv_bfloat162*)(Wlo + base)     = __nv_bfloat162(l0, l1);
                *(__nv_bfloat162*)(Wlo + base + 2) = __nv_bfloat162(l2, l3);
            }
        }
        __syncthreads();

        #pragma unroll
        for (int ks = 0; ks < 4; ks++) {
            int kw = ks * 8 + tig;
            uint32_t ahi[2][4], alo[2][4];
            #pragma unroll
            for (int mt = 0; mt < 2; mt++) {
                int r0 = (w * 32 + mt * 16 + g) * (APITCH / 2) + kw;
                int r1 = r0 + 8 * (APITCH / 2);
                ahi[mt][0] = A32h[r0]; ahi[mt][1] = A32h[r1];
                ahi[mt][2] = A32h[r0 + 4]; ahi[mt][3] = A32h[r1 + 4];
                alo[mt][0] = A32l[r0]; alo[mt][1] = A32l[r1];
                alo[mt][2] = A32l[r0 + 4]; alo[mt][3] = A32l[r1 + 4];
            }
            #pragma unroll
            for (int nt = 0; nt < 8; nt++) {
                int bw = (nt * 8 + g) * (APITCH / 2) + kw;
                uint32_t bh0 = W32h[bw], bh1 = W32h[bw + 4];
                uint32_t bl0 = W32l[bw], bl1 = W32l[bw + 4];
                #pragma unroll
                for (int mt = 0; mt < 2; mt++) {
                    mma_bf16(acc[mt][nt], ahi[mt], bh0, bh1);
                    mma_bf16(acc[mt][nt], ahi[mt], bl0, bl1);
                    mma_bf16(acc[mt][nt], alo[mt], bh0, bh1);
                }
            }
        }
    }

    #pragma unroll
    for (int mt = 0; mt < 2; mt++) {
        int row0 = nb + w * 32 + mt * 16 + g;
        int row1 = row0 + 8;
        #pragma unroll
        for (int nt = 0; nt < 8; nt++) {
            int col = nt * 8 + 2 * tig;
            float b0 = __ldg(&b[col]), b1 = __ldg(&b[col + 1]);
            float v0 = acc[mt][nt][0] + b0, v1 = acc[mt][nt][1] + b1;
            float v2 = acc[mt][nt][2] + b0, v3 = acc[mt][nt][3] + b1;
            if (relu) {
                v0 = fmaxf(v0, 0.f); v1 = fmaxf(v1, 0.f);
                v2 = fmaxf(v2, 0.f); v3 = fmaxf(v3, 0.f);
            }
            if (row0 < NN) *(float2*)(out + (size_t)row0 * 64 + col) = make_float2(v0, v1);
            if (row1 < NN) *(float2*)(out + (size_t)row1 * 64 + col) = make_float2(v2, v3);
        }
    }
}

// ---------------- classifier: [N,64] @ Wc[64,40] + bc ---------------
__global__ void k_classifier(const float* __restrict__ h,
                             const float* __restrict__ Wc,
                             const float* __restrict__ bc,
                             float* __restrict__ out)
{
    __shared__ float Ws[64 * NCLS];
    __shared__ float bs[NCLS];
    for (int i = threadIdx.x; i < 64 * NCLS; i += blockDim.x) Ws[i] = Wc[i];
    for (int i = threadIdx.x; i < NCLS; i += blockDim.x) bs[i] = bc[i];
    __syncthreads();

    int gid = blockIdx.x * blockDim.x + threadIdx.x;
    if (gid >= NN * NCLS) return;
    int n = gid / NCLS;
    int c = gid % NCLS;
    const float* row = h + (size_t)n * 64;
    float acc = bs[c];
    #pragma unroll
    for (int i = 0; i < 64; i++) acc += row[i] * Ws[i * NCLS + c];
    out[gid] = acc;
}

// ---------------- launch ---------------------------------------------
extern "C" void kernel_launch(void* const* d_in, const int* in_sizes, int n_in,
                              void* d_out, int out_size)
{
    const float* x  = (const float*)d_in[0];
    const void*  ei = d_in[1];
    const float* W1 = (const float*)d_in[2];
    const float* b1 = (const float*)d_in[3];
    const float* W2 = (const float*)d_in[4];
    const float* b2 = (const float*)d_in[5];
    const float* Wc = (const float*)d_in[6];
    const float* bc = (const float*)d_in[7];
    float* out = (float*)d_out;

    void* tmp;
    cudaGetSymbolAddress(&tmp, g_cnt);  int*    p_cnt  = (int*)tmp;
    cudaGetSymbolAddress(&tmp, g_fill); int*    p_fill = (int*)tmp;
    cudaGetSymbolAddress(&tmp, g_hop1); float4* p_hop1 = (float4*)tmp;
    cudaGetSymbolAddress(&tmp, g_hop2); float4* p_hop2 = (float4*)tmp;
    cudaGetSymbolAddress(&tmp, g_hop3); float4* p_hop3 = (float4*)tmp;
    cudaGetSymbolAddress(&tmp, g_h1);   float4* p_h1   = (float4*)tmp;
    cudaGetSymbolAddress(&tmp, g_h2);   float4* p_h2   = (float4*)tmp;

    cudaFuncSetAttribute(k_gemm_mma, cudaFuncAttributeMaxDynamicSharedMemorySize,
                         GEMM_SMEM);

    const int EB = (NE + 255) / 256;
    const int SB = (NN * 16 + 255) / 256;   // 16 threads per node (R10 mapping)
    const int NB = (NN + 255) / 256;
    const int GB = (NN + 127) / 128;
    const int CB = (NN * NCLS + 255) / 256;

    // ---- CSR build ----
    k_detect<<<1, 32>>>((const long long*)ei);
    cudaMemsetAsync(p_cnt, 0, NN * sizeof(int));
    cudaMemsetAsync(p_fill, 0, NN * sizeof(int));
    k_convert_hist<<<EB, 256>>>(ei);
    k_dinv<<<NB, 256>>>();
    k_scan1<<<SCAN_NB, 256>>>();
    k_scan2<<<1, 512>>>();
    k_scan3<<<SCAN_NB, 256>>>();
    k_fill<<<EB, 256>>>();

    // ---- layer 1 ----
    k_spmm_csr<<<SB, 256>>>((const float4*)x, p_hop1);
    k_spmm_csr<<<SB, 256>>>(p_hop1, p_hop2);
    k_spmm_csr<<<SB, 256>>>(p_hop2, p_hop3);
    k_gemm_mma<<<GB, 128, GEMM_SMEM>>>((const float4*)x, p_hop1, p_hop2, p_hop3,
                                       W1, b1, (float*)p_h1, 1);

    // ---- layer 2 ----
    k_spmm_csr<<<SB, 256>>>(p_h1, p_hop1);
    k_spmm_csr<<<SB, 256>>>(p_hop1, p_hop2);
    k_spmm_csr<<<SB, 256>>>(p_hop2, p_hop3);
    k_gemm_mma<<<GB, 128, GEMM_SMEM>>>(p_h1, p_hop1, p_hop2, p_hop3,
                                       W2, b2, (float*)p_h2, 1);

    // ---- classifier ----
    k_classifier<<<CB, 256>>>((const float*)p_h2, Wc, bc, out);
}

// round 16
// speedup vs baseline: 1.7918x; 1.2198x over previous
#include <cuda_runtime.h>
#include <cuda_bf16.h>
#include <cstdint>

#define NN 100000
#define NE 1200000
#define FEAT4 16           // 64 floats = 16 float4 per node
#define NCLS 40
#define SCAN_NB 391        // ceil(100000/256)

// ---------------- device scratch (no allocs allowed) ----------------
__device__ int    g_src[NE];
__device__ int    g_dst[NE];
__device__ int    g_cnt[NN];
__device__ int    g_rowptr[NN + 1];
__device__ int    g_fill[NN];
__device__ int    g_bsum[512];
__device__ float  g_dinv[NN];
__device__ int2   g_csr[NE];          // {src, bitcast(weight)} grouped by dst
__device__ float4 g_hop1[NN * FEAT4];
__device__ float4 g_hop2[NN * FEAT4];
__device__ float4 g_hop3[NN * FEAT4];
__device__ float4 g_h1[NN * FEAT4];
__device__ float4 g_h2[NN * FEAT4];
__device__ int    g_is64;

// ---------------- detect dtype + zero cnt ---------------------------
__global__ void k_detect0(const long long* p) {
    int gid = blockIdx.x * blockDim.x + threadIdx.x;
    if (gid < NN) g_cnt[gid] = 0;
    if (gid == 0) {
        int ok = 1;
        #pragma unroll 1
        for (int i = 0; i < 64; i++) {
            long long v = p[i * 997];
            if (v < 0 || v >= NN) { ok = 0; break; }
        }
        g_is64 = ok;
    }
}

// ---------------- convert + degree histogram fused ------------------
__global__ void k_convert_hist(const void* edges) {
    int e = blockIdx.x * blockDim.x + threadIdx.x;
    if (e >= NE) return;
    int s, d;
    if (g_is64) {
        const long long* p = (const long long*)edges;
        s = (int)p[e];
        d = (int)p[e + NE];
    } else {
        const int* p = (const int*)edges;
        s = p[e];
        d = p[e + NE];
    }
    g_src[e] = s;
    g_dst[e] = d;
    atomicAdd(&g_cnt[d], 1);
}

// ---------------- scan pass 1 (+ dinv, + zero fill) -----------------
__global__ void k_scan1() {
    __shared__ int sh[2][256];
    int tid = threadIdx.x;
    int gid = blockIdx.x * 256 + tid;
    int v = (gid < NN) ? g_cnt[gid] : 0;
    if (gid < NN) {
        g_fill[gid] = 0;
        float d = (float)v;
        g_dinv[gid] = (d > 0.f) ? rsqrtf(fmaxf(d, 1.f)) : 0.f;
    }
    sh[0][tid] = v;
    __syncthreads();
    int cur = 0;
    #pragma unroll
    for (int off = 1; off < 256; off <<= 1) {
        int a = sh[cur][tid];
        if (tid >= off) a += sh[cur][tid - off];
        sh[cur ^ 1][tid] = a;
        cur ^= 1;
        __syncthreads();
    }
    int incl = sh[cur][tid];
    if (gid <= NN) g_rowptr[gid] = incl - v;
    if (tid == 255) g_bsum[blockIdx.x] = incl;
}

// ---------------- scan pass 2+3 merged ------------------------------
// Each block redundantly reduces bsum[0..bid) (inclusive block sums from
// scan1) to get its exclusive offset, then applies it.
__global__ void k_scan23() {
    __shared__ int red[256];
    int bid = blockIdx.x;
    int tid = threadIdx.x;
    int s = 0;
    for (int t = tid; t < bid; t += 256) s += g_bsum[t];
    red[tid] = s;
    __syncthreads();
    #pragma unroll
    for (int off = 128; off; off >>= 1) {
        if (tid < off) red[tid] += red[tid + off];
        __syncthreads();
    }
    int offset = red[0];
    int gid = bid * 256 + tid;
    if (gid < NN) g_rowptr[gid] += offset;
    if (gid == 0) g_rowptr[NN] = NE;
}

// ---------------- CSR fill (weight fused) ---------------------------
__global__ void k_fill() {
    int e = blockIdx.x * blockDim.x + threadIdx.x;
    if (e >= NE) return;
    int s = g_src[e];
    int d = g_dst[e];
    int pos = g_rowptr[d] + atomicAdd(&g_fill[d], 1);
    float w = g_dinv[s] * g_dinv[d];
    g_csr[pos] = make_int2(s, __float_as_int(w));
}

// ---------------- SpMM (CSR pull, 16 threads/node, unroll-4) --------
__global__ void __launch_bounds__(256) k_spmm_csr(
    const float4* __restrict__ feat, float4* __restrict__ out)
{
    int gid = blockIdx.x * blockDim.x + threadIdx.x;
    if (gid >= NN * 16) return;
    int node = gid >> 4;
    int q    = gid & 15;
    int beg = g_rowptr[node];
    int end = g_rowptr[node + 1];
    float4 acc = make_float4(0.f, 0.f, 0.f, 0.f);

    int i = beg;
    for (; i + 4 <= end; i += 4) {
        int2 s0 = __ldg(&g_csr[i]);
        int2 s1 = __ldg(&g_csr[i + 1]);
        int2 s2 = __ldg(&g_csr[i + 2]);
        int2 s3 = __ldg(&g_csr[i + 3]);
        float4 v0 = __ldg(&feat[s0.x * FEAT4 + q]);
        float4 v1 = __ldg(&feat[s1.x * FEAT4 + q]);
        float4 v2 = __ldg(&feat[s2.x * FEAT4 + q]);
        float4 v3 = __ldg(&feat[s3.x * FEAT4 + q]);
        float w0 = __int_as_float(s0.y), w1 = __int_as_float(s1.y);
        float w2 = __int_as_float(s2.y), w3 = __int_as_float(s3.y);
        acc.x += w0 * v0.x + w1 * v1.x + w2 * v2.x + w3 * v3.x;
        acc.y += w0 * v0.y + w1 * v1.y + w2 * v2.y + w3 * v3.y;
        acc.z += w0 * v0.z + w1 * v1.z + w2 * v2.z + w3 * v3.z;
        acc.w += w0 * v0.w + w1 * v1.w + w2 * v2.w + w3 * v3.w;
    }
    for (; i < end; i++) {
        int2 sw = __ldg(&g_csr[i]);
        float w = __int_as_float(sw.y);
        float4 v = __ldg(&feat[sw.x * FEAT4 + q]);
        acc.x += w * v.x; acc.y += w * v.y;
        acc.z += w * v.z; acc.w += w * v.w;
    }
    out[node * FEAT4 + q] = acc;
}

// ====================================================================
// HMMA bf16 split-2 GEMM: out[128-tile,64] = concat(hops)[*,256] @ W + b
// ====================================================================
#define APITCH 72
#define A_SZ   (128 * APITCH)
#define W_SZ   (64 * APITCH)
#define OFF_ALO A_SZ
#define OFF_WHI (2 * A_SZ)
#define OFF_WLO (2 * A_SZ + W_SZ)
#define GEMM_SMEM ((2 * A_SZ + 2 * W_SZ) * 2)   // 55296 bytes

__device__ __forceinline__ void bsplit(float x, __nv_bfloat16& h, __nv_bfloat16& l) {
    h = __float2bfloat16(x);
    l = __float2bfloat16(x - __bfloat162float(h));
}

__device__ __forceinline__ void mma_bf16(float* c, const uint32_t* a,
                                         uint32_t b0, uint32_t b1) {
    asm volatile(
        "mma.sync.aligned.m16n8k16.row.col.f32.bf16.bf16.f32 "
        "{%0,%1,%2,%3}, {%4,%5,%6,%7}, {%8,%9}, {%0,%1,%2,%3};"
        : "+f"(c[0]), "+f"(c[1]), "+f"(c[2]), "+f"(c[3])
        : "r"(a[0]), "r"(a[1]), "r"(a[2]), "r"(a[3]), "r"(b0), "r"(b1));
}

__global__ void __launch_bounds__(128) k_gemm_mma(
    const float4* __restrict__ A0, const float4* __restrict__ A1,
    const float4* __restrict__ A2, const float4* __restrict__ A3,
    const float* __restrict__ W, const float* __restrict__ b,
    float* __restrict__ out, int relu)
{
    extern __shared__ __nv_bfloat16 shb[];
    __nv_bfloat16* Ahi = shb;
    __nv_bfloat16* Alo = shb + OFF_ALO;
    __nv_bfloat16* Whi = shb + OFF_WHI;
    __nv_bfloat16* Wlo = shb + OFF_WLO;
    const uint32_t* A32h = (const uint32_t*)Ahi;
    const uint32_t* A32l = (const uint32_t*)Alo;
    const uint32_t* W32h = (const uint32_t*)Whi;
    const uint32_t* W32l = (const uint32_t*)Wlo;

    const int tid  = threadIdx.x;
    const int lane = tid & 31;
    const int w    = tid >> 5;
    const int g    = lane >> 2;
    const int tig  = lane & 3;
    const int nb   = blockIdx.x * 128;

    float acc[2][8][4];
    #pragma unroll
    for (int mt = 0; mt < 2; mt++)
        #pragma unroll
        for (int nt = 0; nt < 8; nt++)
            #pragma unroll
            for (int i = 0; i < 4; i++) acc[mt][nt][i] = 0.f;

    #pragma unroll 1
    for (int c = 0; c < 4; c++) {
        const float4* Ap = (c == 0) ? A0 : (c == 1) ? A1 : (c == 2) ? A2 : A3;
        if (c) __syncthreads();

        {
            int node = nb + tid;
            const float4* row = Ap + (size_t)node * FEAT4;
            #pragma unroll
            for (int j = 0; j < 16; j++) {
                float4 v = (node < NN) ? __ldg(&row[j]) : make_float4(0, 0, 0, 0);
                __nv_bfloat16 h0, h1, h2, h3, l0, l1, l2, l3;
                bsplit(v.x, h0, l0); bsplit(v.y, h1, l1);
                bsplit(v.z, h2, l2); bsplit(v.w, h3, l3);
                int base = tid * APITCH + j * 4;
                *(__nv_bfloat162*)(Ahi + base)     = __nv_bfloat162(h0, h1);
                *(__nv_bfloat162*)(Ahi + base + 2) = __nv_bfloat162(h2, h3);
                *(__nv_bfloat162*)(Alo + base)     = __nv_bfloat162(l0, l1);
                *(__nv_bfloat162*)(Alo + base + 2) = __nv_bfloat162(l2, l3);
            }
        }
        {
            int n    = tid & 63;
            int half = tid >> 6;
            #pragma unroll
            for (int jj = 0; jj < 8; jj++) {
                int k0 = half * 32 + jj * 4;
                float w0 = __ldg(&W[(c * 64 + k0 + 0) * 64 + n]);
                float w1 = __ldg(&W[(c * 64 + k0 + 1) * 64 + n]);
                float w2 = __ldg(&W[(c * 64 + k0 + 2) * 64 + n]);
                float w3 = __ldg(&W[(c * 64 + k0 + 3) * 64 + n]);
                __nv_bfloat16 h0, h1, h2, h3, l0, l1, l2, l3;
                bsplit(w0, h0, l0); bsplit(w1, h1, l1);
                bsplit(w2, h2, l2); bsplit(w3, h3, l3);
                int base = n * APITCH + k0;
                *(__nv_bfloat162*)(Whi + base)     = __nv_bfloat162(h0, h1);
                *(__nv_bfloat162*)(Whi + base + 2) = __nv_bfloat162(h2, h3);
                *(__nv_bfloat162*)(Wlo + base)     = __nv_bfloat162(l0, l1);
                *(__nv_bfloat162*)(Wlo + base + 2) = __nv_bfloat162(l2, l3);
            }
        }
        __syncthreads();

        #pragma unroll
        for (int ks = 0; ks < 4; ks++) {
            int kw = ks * 8 + tig;
            uint32_t ahi[2][4], alo[2][4];
            #pragma unroll
            for (int mt = 0; mt < 2; mt++) {
                int r0 = (w * 32 + mt * 16 + g) * (APITCH / 2) + kw;
                int r1 = r0 + 8 * (APITCH / 2);
                ahi[mt][0] = A32h[r0]; ahi[mt][1] = A32h[r1];
                ahi[mt][2] = A32h[r0 + 4]; ahi[mt][3] = A32h[r1 + 4];
                alo[mt][0] = A32l[r0]; alo[mt][1] = A32l[r1];
                alo[mt][2] = A32l[r0 + 4]; alo[mt][3] = A32l[r1 + 4];
            }
            #pragma unroll
            for (int nt = 0; nt < 8; nt++) {
                int bw = (nt * 8 + g) * (APITCH / 2) + kw;
                uint32_t bh0 = W32h[bw], bh1 = W32h[bw + 4];
                uint32_t bl0 = W32l[bw], bl1 = W32l[bw + 4];
                #pragma unroll
                for (int mt = 0; mt < 2; mt++) {
                    mma_bf16(acc[mt][nt], ahi[mt], bh0, bh1);
                    mma_bf16(acc[mt][nt], ahi[mt], bl0, bl1);
                    mma_bf16(acc[mt][nt], alo[mt], bh0, bh1);
                }
            }
        }
    }

    #pragma unroll
    for (int mt = 0; mt < 2; mt++) {
        int row0 = nb + w * 32 + mt * 16 + g;
        int row1 = row0 + 8;
        #pragma unroll
        for (int nt = 0; nt < 8; nt++) {
            int col = nt * 8 + 2 * tig;
            float b0 = __ldg(&b[col]), b1 = __ldg(&b[col + 1]);
            float v0 = acc[mt][nt][0] + b0, v1 = acc[mt][nt][1] + b1;
            float v2 = acc[mt][nt][2] + b0, v3 = acc[mt][nt][3] + b1;
            if (relu) {
                v0 = fmaxf(v0, 0.f); v1 = fmaxf(v1, 0.f);
                v2 = fmaxf(v2, 0.f); v3 = fmaxf(v3, 0.f);
            }
            if (row0 < NN) *(float2*)(out + (size_t)row0 * 64 + col) = make_float2(v0, v1);
            if (row1 < NN) *(float2*)(out + (size_t)row1 * 64 + col) = make_float2(v2, v3);
        }
    }
}

// ====================================================================
// Classifier via HMMA split-2: out[128-tile,40] = h2[*,64] @ Wc + bc
// Single K=64 chunk; N padded (nt<5 covers cols 0..39).
// ====================================================================
__global__ void __launch_bounds__(128) k_cls_mma(
    const float4* __restrict__ A0,
    const float* __restrict__ W, const float* __restrict__ b,
    float* __restrict__ out)
{
    extern __shared__ __nv_bfloat16 shb[];
    __nv_bfloat16* Ahi = shb;
    __nv_bfloat16* Alo = shb + OFF_ALO;
    __nv_bfloat16* Whi = shb + OFF_WHI;
    __nv_bfloat16* Wlo = shb + OFF_WLO;
    const uint32_t* A32h = (const uint32_t*)Ahi;
    const uint32_t* A32l = (const uint32_t*)Alo;
    const uint32_t* W32h = (const uint32_t*)Whi;
    const uint32_t* W32l = (const uint32_t*)Wlo;

    const int tid  = threadIdx.x;
    const int lane = tid & 31;
    const int w    = tid >> 5;
    const int g    = lane >> 2;
    const int tig  = lane & 3;
    const int nb   = blockIdx.x * 128;

    float acc[2][5][4];
    #pragma unroll
    for (int mt = 0; mt < 2; mt++)
        #pragma unroll
        for (int nt = 0; nt < 5; nt++)
            #pragma unroll
            for (int i = 0; i < 4; i++) acc[mt][nt][i] = 0.f;

    {
        int node = nb + tid;
        const float4* row = A0 + (size_t)node * FEAT4;
        #pragma unroll
        for (int j = 0; j < 16; j++) {
            float4 v = (node < NN) ? __ldg(&row[j]) : make_float4(0, 0, 0, 0);
            __nv_bfloat16 h0, h1, h2, h3, l0, l1, l2, l3;
            bsplit(v.x, h0, l0); bsplit(v.y, h1, l1);
            bsplit(v.z, h2, l2); bsplit(v.w, h3, l3);
            int base = tid * APITCH + j * 4;
            *(__nv_bfloat162*)(Ahi + base)     = __nv_bfloat162(h0, h1);
            *(__nv_bfloat162*)(Ahi + base + 2) = __nv_bfloat162(h2, h3);
            *(__nv_bfloat162*)(Alo + base)     = __nv_bfloat162(l0, l1);
            *(__nv_bfloat162*)(Alo + base + 2) = __nv_bfloat162(l2, l3);
        }
    }
    {
        int n    = tid & 63;
        int half = tid >> 6;
        bool nv  = (n < NCLS);
        #pragma unroll
        for (int jj = 0; jj < 8; jj++) {
            int k0 = half * 32 + jj * 4;
            float w0 = nv ? __ldg(&W[(k0 + 0) * NCLS + n]) : 0.f;
            float w1 = nv ? __ldg(&W[(k0 + 1) * NCLS + n]) : 0.f;
            float w2 = nv ? __ldg(&W[(k0 + 2) * NCLS + n]) : 0.f;
            float w3 = nv ? __ldg(&W[(k0 + 3) * NCLS + n]) : 0.f;
            __nv_bfloat16 h0, h1, h2, h3, l0, l1, l2, l3;
            bsplit(w0, h0, l0); bsplit(w1, h1, l1);
            bsplit(w2, h2, l2); bsplit(w3, h3, l3);
            int base = n * APITCH + k0;
            *(__nv_bfloat162*)(Whi + base)     = __nv_bfloat162(h0, h1);
            *(__nv_bfloat162*)(Whi + base + 2) = __nv_bfloat162(h2, h3);
            *(__nv_bfloat162*)(Wlo + base)     = __nv_bfloat162(l0, l1);
            *(__nv_bfloat162*)(Wlo + base + 2) = __nv_bfloat162(l2, l3);
        }
    }
    __syncthreads();

    #pragma unroll
    for (int ks = 0; ks < 4; ks++) {
        int kw = ks * 8 + tig;
        uint32_t ahi[2][4], alo[2][4];
        #pragma unroll
        for (int mt = 0; mt < 2; mt++) {
            int r0 = (w * 32 + mt * 16 + g) * (APITCH / 2) + kw;
            int r1 = r0 + 8 * (APITCH / 2);
            ahi[mt][0] = A32h[r0]; ahi[mt][1] = A32h[r1];
            ahi[mt][2] = A32h[r0 + 4]; ahi[mt][3] = A32h[r1 + 4];
            alo[mt][0] = A32l[r0]; alo[mt][1] = A32l[r1];
            alo[mt][2] = A32l[r0 + 4]; alo[mt][3] = A32l[r1 + 4];
        }
        #pragma unroll
        for (int nt = 0; nt < 5; nt++) {
            int bw = (nt * 8 + g) * (APITCH / 2) + kw;
            uint32_t bh0 = W32h[bw], bh1 = W32h[bw + 4];
            uint32_t bl0 = W32l[bw], bl1 = W32l[bw + 4];
            #pragma unroll
            for (int mt = 0; mt < 2; mt++) {
                mma_bf16(acc[mt][nt], ahi[mt], bh0, bh1);
                mma_bf16(acc[mt][nt], ahi[mt], bl0, bl1);
                mma_bf16(acc[mt][nt], alo[mt], bh0, bh1);
            }
        }
    }

    #pragma unroll
    for (int mt = 0; mt < 2; mt++) {
        int row0 = nb + w * 32 + mt * 16 + g;
        int row1 = row0 + 8;
        #pragma unroll
        for (int nt = 0; nt < 5; nt++) {
            int col = nt * 8 + 2 * tig;
            if (col + 1 < NCLS) {
                float b0 = __ldg(&b[col]), b1 = __ldg(&b[col + 1]);
                float v0 = acc[mt][nt][0] + b0, v1 = acc[mt][nt][1] + b1;
                float v2 = acc[mt][nt][2] + b0, v3 = acc[mt][nt][3] + b1;
                if (row0 < NN) *(float2*)(out + (size_t)row0 * NCLS + col) = make_float2(v0, v1);
                if (row1 < NN) *(float2*)(out + (size_t)row1 * NCLS + col) = make_float2(v2, v3);
            }
        }
    }
}

// ---------------- launch ---------------------------------------------
extern "C" void kernel_launch(void* const* d_in, const int* in_sizes, int n_in,
                              void* d_out, int out_size)
{
    const float* x  = (const float*)d_in[0];
    const void*  ei = d_in[1];
    const float* W1 = (const float*)d_in[2];
    const float* b1 = (const float*)d_in[3];
    const float* W2 = (const float*)d_in[4];
    const float* b2 = (const float*)d_in[5];
    const float* Wc = (const float*)d_in[6];
    const float* bc = (const float*)d_in[7];
    float* out = (float*)d_out;

    void* tmp;
    cudaGetSymbolAddress(&tmp, g_hop1); float4* p_hop1 = (float4*)tmp;
    cudaGetSymbolAddress(&tmp, g_hop2); float4* p_hop2 = (float4*)tmp;
    cudaGetSymbolAddress(&tmp, g_hop3); float4* p_hop3 = (float4*)tmp;
    cudaGetSymbolAddress(&tmp, g_h1);   float4* p_h1   = (float4*)tmp;
    cudaGetSymbolAddress(&tmp, g_h2);   float4* p_h2   = (float4*)tmp;

    cudaFuncSetAttribute(k_gemm_mma, cudaFuncAttributeMaxDynamicSharedMemorySize,
                         GEMM_SMEM);
    cudaFuncSetAttribute(k_cls_mma, cudaFuncAttributeMaxDynamicSharedMemorySize,
                         GEMM_SMEM);

    const int EB = (NE + 255) / 256;
    const int SB = (NN * 16 + 255) / 256;
    const int NB = (NN + 255) / 256;
    const int GB = (NN + 127) / 128;

    // ---- CSR build (5 launches) ----
    k_detect0<<<NB, 256>>>((const long long*)ei);
    k_convert_hist<<<EB, 256>>>(ei);
    k_scan1<<<SCAN_NB, 256>>>();
    k_scan23<<<SCAN_NB, 256>>>();
    k_fill<<<EB, 256>>>();

    // ---- layer 1 ----
    k_spmm_csr<<<SB, 256>>>((const float4*)x, p_hop1);   // launch #6: profiled
    k_spmm_csr<<<SB, 256>>>(p_hop1, p_hop2);
    k_spmm_csr<<<SB, 256>>>(p_hop2, p_hop3);
    k_gemm_mma<<<GB, 128, GEMM_SMEM>>>((const float4*)x, p_hop1, p_hop2, p_hop3,
                                       W1, b1, (float*)p_h1, 1);

    // ---- layer 2 ----
    k_spmm_csr<<<SB, 256>>>(p_h1, p_hop1);
    k_spmm_csr<<<SB, 256>>>(p_hop1, p_hop2);
    k_spmm_csr<<<SB, 256>>>(p_hop2, p_hop3);
    k_gemm_mma<<<GB, 128, GEMM_SMEM>>>(p_h1, p_hop1, p_hop2, p_hop3,
                                       W2, b2, (float*)p_h2, 1);

    // ---- classifier ----
    k_cls_mma<<<GB, 128, GEMM_SMEM>>>(p_h2, Wc, bc, out);
}

// round 17
// speedup vs baseline: 1.8265x; 1.0194x over previous
#include <cuda_runtime.h>
#include <cuda_bf16.h>
#include <cstdint>

#define NN 100000
#define NE 1200000
#define FEAT4 16           // 64 floats = 16 float4 per node (fp32 inputs)
#define NCLS 40
#define SCAN_NB 391        // ceil(100000/256)

// ---------------- device scratch (no allocs allowed) ----------------
__device__ int    g_cnt[NN];
__device__ int    g_rowptr[NN + 1];
__device__ int    g_fill[NN];
__device__ int    g_bsum[512];
__device__ float  g_dinv[NN];
__device__ int2   g_csr[NE];          // {src, bitcast(weight)} grouped by dst

// split-bf16 feature planes: [node][64] bf16 = 32 words/row
__device__ __nv_bfloat162 g_hop1h[NN * 32], g_hop1l[NN * 32];
__device__ __nv_bfloat162 g_hop2h[NN * 32], g_hop2l[NN * 32];
__device__ __nv_bfloat162 g_hop3h[NN * 32], g_hop3l[NN * 32];
__device__ __nv_bfloat162 g_h1h[NN * 32],  g_h1l[NN * 32];
__device__ __nv_bfloat162 g_h2h[NN * 32],  g_h2l[NN * 32];

// pre-split weights, padded stride 72 ([n][k] order, chunked)
__device__ __nv_bfloat16 g_w1h[4 * 64 * 72], g_w1l[4 * 64 * 72];
__device__ __nv_bfloat16 g_w2h[4 * 64 * 72], g_w2l[4 * 64 * 72];
__device__ __nv_bfloat16 g_wch[64 * 72],     g_wcl[64 * 72];

// ---------------- helpers -------------------------------------------
__device__ __forceinline__ int detect64(const long long* p) {
    int ok = 1;
    #pragma unroll 8
    for (int i = 0; i < 64; i++) {
        long long v = p[i * 997];
        ok &= (v >= 0 && v < NN);
    }
    return ok;
}

__device__ __forceinline__ void bsplit(float x, __nv_bfloat16& h, __nv_bfloat16& l) {
    h = __float2bfloat16(x);
    l = __float2bfloat16(x - __bfloat162float(h));
}

__device__ __forceinline__ void wsplit2(float a, float b,
                                        __nv_bfloat162& h, __nv_bfloat162& l) {
    __nv_bfloat16 ha, la, hb, lb;
    bsplit(a, ha, la);
    bsplit(b, hb, lb);
    h = __nv_bfloat162(ha, hb);
    l = __nv_bfloat162(la, lb);
}

// unpack bf16x2 word -> two floats (shift/AND, no cvt)
__device__ __forceinline__ void unpk(uint32_t w, float& e0, float& e1) {
    e0 = __uint_as_float(w << 16);
    e1 = __uint_as_float(w & 0xFFFF0000u);
}

// ---------------- k_wsplit: split weights + zero g_cnt --------------
__global__ void k_wsplit(const float* __restrict__ W1,
                         const float* __restrict__ W2,
                         const float* __restrict__ Wc)
{
    int t = blockIdx.x * blockDim.x + threadIdx.x;
    if (t < NN) g_cnt[t] = 0;
    if (t < 16384) {                 // W1: 4 chunks x 64k x 64n
        int c = t >> 12, rem = t & 4095, k = rem >> 6, n = rem & 63;
        __nv_bfloat16 h, l;
        bsplit(W1[(c * 64 + k) * 64 + n], h, l);
        g_w1h[c * 4608 + n * 72 + k] = h;
        g_w1l[c * 4608 + n * 72 + k] = l;
    } else if (t < 32768) {
        int u = t - 16384;
        int c = u >> 12, rem = u & 4095, k = rem >> 6, n = rem & 63;
        __nv_bfloat16 h, l;
        bsplit(W2[(c * 64 + k) * 64 + n], h, l);
        g_w2h[c * 4608 + n * 72 + k] = h;
        g_w2l[c * 4608 + n * 72 + k] = l;
    } else if (t < 36864) {          // Wc: 64k x 64n (n>=40 zero)
        int u = t - 32768;
        int k = u >> 6, n = u & 63;
        float v = (n < NCLS) ? Wc[k * NCLS + n] : 0.f;
        __nv_bfloat16 h, l;
        bsplit(v, h, l);
        g_wch[n * 72 + k] = h;
        g_wcl[n * 72 + k] = l;
    }
}

// ---------------- histogram (reads edges directly) ------------------
__global__ void k_hist(const void* edges) {
    __shared__ int s64;
    if (threadIdx.x == 0) s64 = detect64((const long long*)edges);
    __syncthreads();
    int e = blockIdx.x * blockDim.x + threadIdx.x;
    if (e >= NE) return;
    int d = s64 ? (int)((const long long*)edges)[e + NE]
                : ((const int*)edges)[e + NE];
    atomicAdd(&g_cnt[d], 1);
}

// ---------------- scan pass 1 (+ dinv, + zero fill) -----------------
__global__ void k_scan1() {
    __shared__ int sh[2][256];
    int tid = threadIdx.x;
    int gid = blockIdx.x * 256 + tid;
    int v = (gid < NN) ? g_cnt[gid] : 0;
    if (gid < NN) {
        g_fill[gid] = 0;
        float d = (float)v;
        g_dinv[gid] = (d > 0.f) ? rsqrtf(fmaxf(d, 1.f)) : 0.f;
    }
    sh[0][tid] = v;
    __syncthreads();
    int cur = 0;
    #pragma unroll
    for (int off = 1; off < 256; off <<= 1) {
        int a = sh[cur][tid];
        if (tid >= off) a += sh[cur][tid - off];
        sh[cur ^ 1][tid] = a;
        cur ^= 1;
        __syncthreads();
    }
    int incl = sh[cur][tid];
    if (gid <= NN) g_rowptr[gid] = incl - v;
    if (tid == 255) g_bsum[blockIdx.x] = incl;
}

// ---------------- scan pass 2+3 merged ------------------------------
__global__ void k_scan23() {
    __shared__ int red[256];
    int bid = blockIdx.x;
    int tid = threadIdx.x;
    int s = 0;
    for (int t = tid; t < bid; t += 256) s += g_bsum[t];
    red[tid] = s;
    __syncthreads();
    #pragma unroll
    for (int off = 128; off; off >>= 1) {
        if (tid < off) red[tid] += red[tid + off];
        __syncthreads();
    }
    int offset = red[0];
    int gid = bid * 256 + tid;
    if (gid < NN) g_rowptr[gid] += offset;
    if (gid == 0) g_rowptr[NN] = NE;
}

// ---------------- CSR fill (reads edges directly) -------------------
__global__ void k_fill(const void* edges) {
    __shared__ int s64;
    if (threadIdx.x == 0) s64 = detect64((const long long*)edges);
    __syncthreads();
    int e = blockIdx.x * blockDim.x + threadIdx.x;
    if (e >= NE) return;
    int s, d;
    if (s64) {
        const long long* p = (const long long*)edges;
        s = (int)p[e]; d = (int)p[e + NE];
    } else {
        const int* p = (const int*)edges;
        s = p[e]; d = p[e + NE];
    }
    int pos = g_rowptr[d] + atomicAdd(&g_fill[d], 1);
    float w = g_dinv[s] * g_dinv[d];
    g_csr[pos] = make_int2(s, __float_as_int(w));
}

// ---------------- split-store for SpMM outputs ----------------------
__device__ __forceinline__ void spmm_store(__nv_bfloat162* oh, __nv_bfloat162* ol,
                                           int node, int q, const float4& acc)
{
    __nv_bfloat162 h0, l0, h1, l1;
    wsplit2(acc.x, acc.y, h0, l0);
    wsplit2(acc.z, acc.w, h1, l1);
    int base = node * 32 + 2 * q;
    oh[base] = h0; oh[base + 1] = h1;
    ol[base] = l0; ol[base + 1] = l1;
}

// ---------------- SpMM from fp32 x (first hop) ----------------------
__global__ void __launch_bounds__(256) k_spmm_f(
    const float4* __restrict__ feat,
    __nv_bfloat162* __restrict__ oh, __nv_bfloat162* __restrict__ ol)
{
    int gid = blockIdx.x * blockDim.x + threadIdx.x;
    if (gid >= NN * 16) return;
    int node = gid >> 4;
    int q    = gid & 15;
    int beg = g_rowptr[node];
    int end = g_rowptr[node + 1];
    float4 acc = make_float4(0.f, 0.f, 0.f, 0.f);
    int i = beg;
    for (; i + 4 <= end; i += 4) {
        int2 s0 = __ldg(&g_csr[i]);
        int2 s1 = __ldg(&g_csr[i + 1]);
        int2 s2 = __ldg(&g_csr[i + 2]);
        int2 s3 = __ldg(&g_csr[i + 3]);
        float4 v0 = __ldg(&feat[s0.x * FEAT4 + q]);
        float4 v1 = __ldg(&feat[s1.x * FEAT4 + q]);
        float4 v2 = __ldg(&feat[s2.x * FEAT4 + q]);
        float4 v3 = __ldg(&feat[s3.x * FEAT4 + q]);
        float w0 = __int_as_float(s0.y), w1 = __int_as_float(s1.y);
        float w2 = __int_as_float(s2.y), w3 = __int_as_float(s3.y);
        acc.x += w0 * v0.x + w1 * v1.x + w2 * v2.x + w3 * v3.x;
        acc.y += w0 * v0.y + w1 * v1.y + w2 * v2.y + w3 * v3.y;
        acc.z += w0 * v0.z + w1 * v1.z + w2 * v2.z + w3 * v3.z;
        acc.w += w0 * v0.w + w1 * v1.w + w2 * v2.w + w3 * v3.w;
    }
    for (; i < end; i++) {
        int2 sw = __ldg(&g_csr[i]);
        float w = __int_as_float(sw.y);
        float4 v = __ldg(&feat[sw.x * FEAT4 + q]);
        acc.x += w * v.x; acc.y += w * v.y;
        acc.z += w * v.z; acc.w += w * v.w;
    }
    spmm_store(oh, ol, node, q, acc);
}

// ---------------- SpMM from split planes ----------------------------
__device__ __forceinline__ float4 gather_split(const uint2* fh, const uint2* fl,
                                               int src, int q, float w, float4 acc)
{
    uint2 h = __ldg(&fh[src * 16 + q]);
    uint2 l = __ldg(&fl[src * 16 + q]);
    float h0, h1, h2, h3, l0, l1, l2, l3;
    unpk(h.x, h0, h1); unpk(h.y, h2, h3);
    unpk(l.x, l0, l1); unpk(l.y, l2, l3);
    acc.x += w * (h0 + l0);
    acc.y += w * (h1 + l1);
    acc.z += w * (h2 + l2);
    acc.w += w * (h3 + l3);
    return acc;
}

__global__ void __launch_bounds__(256) k_spmm_s(
    const __nv_bfloat162* __restrict__ fh_, const __nv_bfloat162* __restrict__ fl_,
    __nv_bfloat162* __restrict__ oh, __nv_bfloat162* __restrict__ ol)
{
    const uint2* fh = (const uint2*)fh_;
    const uint2* fl = (const uint2*)fl_;
    int gid = blockIdx.x * blockDim.x + threadIdx.x;
    if (gid >= NN * 16) return;
    int node = gid >> 4;
    int q    = gid & 15;
    int beg = g_rowptr[node];
    int end = g_rowptr[node + 1];
    float4 acc = make_float4(0.f, 0.f, 0.f, 0.f);
    int i = beg;
    for (; i + 4 <= end; i += 4) {
        int2 s0 = __ldg(&g_csr[i]);
        int2 s1 = __ldg(&g_csr[i + 1]);
        int2 s2 = __ldg(&g_csr[i + 2]);
        int2 s3 = __ldg(&g_csr[i + 3]);
        acc = gather_split(fh, fl, s0.x, q, __int_as_float(s0.y), acc);
        acc = gather_split(fh, fl, s1.x, q, __int_as_float(s1.y), acc);
        acc = gather_split(fh, fl, s2.x, q, __int_as_float(s2.y), acc);
        acc = gather_split(fh, fl, s3.x, q, __int_as_float(s3.y), acc);
    }
    for (; i < end; i++) {
        int2 sw = __ldg(&g_csr[i]);
        acc = gather_split(fh, fl, sw.x, q, __int_as_float(sw.y), acc);
    }
    spmm_store(oh, ol, node, q, acc);
}

// ====================================================================
// HMMA bf16 split-2 GEMM (copy-fill from pre-split planes)
// ====================================================================
#define APITCH 72
#define A_SZ   (128 * APITCH)
#define W_SZ   (64 * APITCH)
#define OFF_ALO A_SZ
#define OFF_WHI (2 * A_SZ)
#define OFF_WLO (2 * A_SZ + W_SZ)
#define GEMM_SMEM ((2 * A_SZ + 2 * W_SZ) * 2)   // 55296 bytes

__device__ __forceinline__ void mma_bf16(float* c, const uint32_t* a,
                                         uint32_t b0, uint32_t b1) {
    asm volatile(
        "mma.sync.aligned.m16n8k16.row.col.f32.bf16.bf16.f32 "
        "{%0,%1,%2,%3}, {%4,%5,%6,%7}, {%8,%9}, {%0,%1,%2,%3};"
        : "+f"(c[0]), "+f"(c[1]), "+f"(c[2]), "+f"(c[3])
        : "r"(a[0]), "r"(a[1]), "r"(a[2]), "r"(a[3]), "r"(b0), "r"(b1));
}

// copy one node row (8 uint4 per plane) from split planes into SMEM
__device__ __forceinline__ void fill_A_copy(
    __nv_bfloat16* Ahi, __nv_bfloat16* Alo,
    const __nv_bfloat162* ph, const __nv_bfloat162* pl, int node, int tid)
{
    uint4* dh = (uint4*)(Ahi + tid * APITCH);
    uint4* dl = (uint4*)(Alo + tid * APITCH);
    if (node < NN) {
        const uint4* sh = (const uint4*)(ph + node * 32);
        const uint4* sl = (const uint4*)(pl + node * 32);
        #pragma unroll
        for (int j = 0; j < 8; j++) { dh[j] = __ldg(&sh[j]); dl[j] = __ldg(&sl[j]); }
    } else {
        uint4 z = make_uint4(0, 0, 0, 0);
        #pragma unroll
        for (int j = 0; j < 8; j++) { dh[j] = z; dl[j] = z; }
    }
}

// fp32 row -> split into SMEM
__device__ __forceinline__ void fill_A_f32(
    __nv_bfloat16* Ahi, __nv_bfloat16* Alo,
    const float4* Ap, int node, int tid)
{
    const float4* row = Ap + (size_t)node * FEAT4;
    #pragma unroll
    for (int j = 0; j < 16; j++) {
        float4 v = (node < NN) ? __ldg(&row[j]) : make_float4(0, 0, 0, 0);
        __nv_bfloat162 h0, l0, h1, l1;
        wsplit2(v.x, v.y, h0, l0);
        wsplit2(v.z, v.w, h1, l1);
        int base = tid * APITCH + j * 4;
        *(__nv_bfloat162*)(Ahi + base)     = h0;
        *(__nv_bfloat162*)(Ahi + base + 2) = h1;
        *(__nv_bfloat162*)(Alo + base)     = l0;
        *(__nv_bfloat162*)(Alo + base + 2) = l1;
    }
}

// copy pre-split W chunk (576 uint4 per plane) into SMEM
__device__ __forceinline__ void fill_W_copy(
    __nv_bfloat16* Whi, __nv_bfloat16* Wlo,
    const __nv_bfloat16* wh, const __nv_bfloat16* wl, int tid)
{
    const uint4* sh = (const uint4*)wh;
    const uint4* sl = (const uint4*)wl;
    uint4* dh = (uint4*)Whi;
    uint4* dl = (uint4*)Wlo;
    #pragma unroll
    for (int j = 0; j < 5; j++) {
        int idx = j * 128 + tid;
        if (idx < 576) { dh[idx] = __ldg(&sh[idx]); dl[idx] = __ldg(&sl[idx]); }
    }
}

// layer GEMM: 4 chunks; chunk0 fp32 (A0f) if non-null else split planes.
__global__ void __launch_bounds__(128) k_gemm_mma(
    const float4* __restrict__ A0f,
    const __nv_bfloat162* __restrict__ A0h, const __nv_bfloat162* __restrict__ A0l,
    const __nv_bfloat162* __restrict__ A1h, const __nv_bfloat162* __restrict__ A1l,
    const __nv_bfloat162* __restrict__ A2h, const __nv_bfloat162* __restrict__ A2l,
    const __nv_bfloat162* __restrict__ A3h, const __nv_bfloat162* __restrict__ A3l,
    const __nv_bfloat16* __restrict__ Wh, const __nv_bfloat16* __restrict__ Wl,
    const float* __restrict__ b,
    __nv_bfloat162* __restrict__ oh, __nv_bfloat162* __restrict__ ol)
{
    extern __shared__ __nv_bfloat16 shb[];
    __nv_bfloat16* Ahi = shb;
    __nv_bfloat16* Alo = shb + OFF_ALO;
    __nv_bfloat16* Whi = shb + OFF_WHI;
    __nv_bfloat16* Wlo = shb + OFF_WLO;
    const uint32_t* A32h = (const uint32_t*)Ahi;
    const uint32_t* A32l = (const uint32_t*)Alo;
    const uint32_t* W32h = (const uint32_t*)Whi;
    const uint32_t* W32l = (const uint32_t*)Wlo;

    const int tid  = threadIdx.x;
    const int lane = tid & 31;
    const int w    = tid >> 5;
    const int g    = lane >> 2;
    const int tig  = lane & 3;
    const int nb   = blockIdx.x * 128;

    const __nv_bfloat162* chh[4] = { A0h, A1h, A2h, A3h };
    const __nv_bfloat162* chl[4] = { A0l, A1l, A2l, A3l };

    float acc[2][8][4];
    #pragma unroll
    for (int mt = 0; mt < 2; mt++)
        #pragma unroll
        for (int nt = 0; nt < 8; nt++)
            #pragma unroll
            for (int i = 0; i < 4; i++) acc[mt][nt][i] = 0.f;

    #pragma unroll 1
    for (int c = 0; c < 4; c++) {
        if (c) __syncthreads();
        int node = nb + tid;
        if (c == 0 && A0f) fill_A_f32(Ahi, Alo, A0f, node, tid);
        else               fill_A_copy(Ahi, Alo, chh[c], chl[c], node, tid);
        fill_W_copy(Whi, Wlo, Wh + c * 4608, Wl + c * 4608, tid);
        __syncthreads();

        #pragma unroll
        for (int ks = 0; ks < 4; ks++) {
            int kw = ks * 8 + tig;
            uint32_t ahi[2][4], alo[2][4];
            #pragma unroll
            for (int mt = 0; mt < 2; mt++) {
                int r0 = (w * 32 + mt * 16 + g) * (APITCH / 2) + kw;
                int r1 = r0 + 8 * (APITCH / 2);
                ahi[mt][0] = A32h[r0]; ahi[mt][1] = A32h[r1];
                ahi[mt][2] = A32h[r0 + 4]; ahi[mt][3] = A32h[r1 + 4];
                alo[mt][0] = A32l[r0]; alo[mt][1] = A32l[r1];
                alo[mt][2] = A32l[r0 + 4]; alo[mt][3] = A32l[r1 + 4];
            }
            #pragma unroll
            for (int nt = 0; nt < 8; nt++) {
                int bw = (nt * 8 + g) * (APITCH / 2) + kw;
                uint32_t bh0 = W32h[bw], bh1 = W32h[bw + 4];
                uint32_t bl0 = W32l[bw], bl1 = W32l[bw + 4];
                #pragma unroll
                for (int mt = 0; mt < 2; mt++) {
                    mma_bf16(acc[mt][nt], ahi[mt], bh0, bh1);
                    mma_bf16(acc[mt][nt], ahi[mt], bl0, bl1);
                    mma_bf16(acc[mt][nt], alo[mt], bh0, bh1);
                }
            }
        }
    }

    // epilogue: bias + relu -> split planes
    #pragma unroll
    for (int mt = 0; mt < 2; mt++) {
        int row0 = nb + w * 32 + mt * 16 + g;
        int row1 = row0 + 8;
        #pragma unroll
        for (int nt = 0; nt < 8; nt++) {
            int col = nt * 8 + 2 * tig;
            int wi  = col >> 1;
            float b0 = __ldg(&b[col]), b1 = __ldg(&b[col + 1]);
            float v0 = fmaxf(acc[mt][nt][0] + b0, 0.f);
            float v1 = fmaxf(acc[mt][nt][1] + b1, 0.f);
            float v2 = fmaxf(acc[mt][nt][2] + b0, 0.f);
            float v3 = fmaxf(acc[mt][nt][3] + b1, 0.f);
            __nv_bfloat162 h, l;
            if (row0 < NN) {
                wsplit2(v0, v1, h, l);
                oh[row0 * 32 + wi] = h; ol[row0 * 32 + wi] = l;
            }
            if (row1 < NN) {
                wsplit2(v2, v3, h, l);
                oh[row1 * 32 + wi] = h; ol[row1 * 32 + wi] = l;
            }
        }
    }
}

// classifier: h2 split planes @ pre-split Wc -> fp32 out
__global__ void __launch_bounds__(128) k_cls_mma(
    const __nv_bfloat162* __restrict__ Ah, const __nv_bfloat162* __restrict__ Al,
    const float* __restrict__ b, float* __restrict__ out)
{
    extern __shared__ __nv_bfloat16 shb[];
    __nv_bfloat16* Ahi = shb;
    __nv_bfloat16* Alo = shb + OFF_ALO;
    __nv_bfloat16* Whi = shb + OFF_WHI;
    __nv_bfloat16* Wlo = shb + OFF_WLO;
    const uint32_t* A32h = (const uint32_t*)Ahi;
    const uint32_t* A32l = (const uint32_t*)Alo;
    const uint32_t* W32h = (const uint32_t*)Whi;
    const uint32_t* W32l = (const uint32_t*)Wlo;

    const int tid  = threadIdx.x;
    const int lane = tid & 31;
    const int w    = tid >> 5;
    const int g    = lane >> 2;
    const int tig  = lane & 3;
    const int nb   = blockIdx.x * 128;

    float acc[2][5][4];
    #pragma unroll
    for (int mt = 0; mt < 2; mt++)
        #pragma unroll
        for (int nt = 0; nt < 5; nt++)
            #pragma unroll
            for (int i = 0; i < 4; i++) acc[mt][nt][i] = 0.f;

    fill_A_copy(Ahi, Alo, Ah, Al, nb + tid, tid);
    fill_W_copy(Whi, Wlo, g_wch, g_wcl, tid);
    __syncthreads();

    #pragma unroll
    for (int ks = 0; ks < 4; ks++) {
        int kw = ks * 8 + tig;
        uint32_t ahi[2][4], alo[2][4];
        #pragma unroll
        for (int mt = 0; mt < 2; mt++) {
            int r0 = (w * 32 + mt * 16 + g) * (APITCH / 2) + kw;
            int r1 = r0 + 8 * (APITCH / 2);
            ahi[mt][0] = A32h[r0]; ahi[mt][1] = A32h[r1];
            ahi[mt][2] = A32h[r0 + 4]; ahi[mt][3] = A32h[r1 + 4];
            alo[mt][0] = A32l[r0]; alo[mt][1] = A32l[r1];
            alo[mt][2] = A32l[r0 + 4]; alo[mt][3] = A32l[r1 + 4];
        }
        #pragma unroll
        for (int nt = 0; nt < 5; nt++) {
            int bw = (nt * 8 + g) * (APITCH / 2) + kw;
            uint32_t bh0 = W32h[bw], bh1 = W32h[bw + 4];
            uint32_t bl0 = W32l[bw], bl1 = W32l[bw + 4];
            #pragma unroll
            for (int mt = 0; mt < 2; mt++) {
                mma_bf16(acc[mt][nt], ahi[mt], bh0, bh1);
                mma_bf16(acc[mt][nt], ahi[mt], bl0, bl1);
                mma_bf16(acc[mt][nt], alo[mt], bh0, bh1);
            }
        }
    }

    #pragma unroll
    for (int mt = 0; mt < 2; mt++) {
        int row0 = nb + w * 32 + mt * 16 + g;
        int row1 = row0 + 8;
        #pragma unroll
        for (int nt = 0; nt < 5; nt++) {
            int col = nt * 8 + 2 * tig;
            float b0 = __ldg(&b[col]), b1 = __ldg(&b[col + 1]);
            float v0 = acc[mt][nt][0] + b0, v1 = acc[mt][nt][1] + b1;
            float v2 = acc[mt][nt][2] + b0, v3 = acc[mt][nt][3] + b1;
            if (row0 < NN) *(float2*)(out + (size_t)row0 * NCLS + col) = make_float2(v0, v1);
            if (row1 < NN) *(float2*)(out + (size_t)row1 * NCLS + col) = make_float2(v2, v3);
        }
    }
}

// ---------------- launch ---------------------------------------------
extern "C" void kernel_launch(void* const* d_in, const int* in_sizes, int n_in,
                              void* d_out, int out_size)
{
    const float* x  = (const float*)d_in[0];
    const void*  ei = d_in[1];
    const float* W1 = (const float*)d_in[2];
    const float* b1 = (const float*)d_in[3];
    const float* W2 = (const float*)d_in[4];
    const float* b2 = (const float*)d_in[5];
    const float* Wc = (const float*)d_in[6];
    const float* bc = (const float*)d_in[7];
    float* out = (float*)d_out;

    void* tmp;
    __nv_bfloat162 *h1h, *h1l, *h2h, *h2l, *p1h, *p1l, *p2h, *p2l, *p3h, *p3l;
    __nv_bfloat16 *w1h, *w1l, *w2h, *w2l;
    cudaGetSymbolAddress(&tmp, g_hop1h); p1h = (__nv_bfloat162*)tmp;
    cudaGetSymbolAddress(&tmp, g_hop1l); p1l = (__nv_bfloat162*)tmp;
    cudaGetSymbolAddress(&tmp, g_hop2h); p2h = (__nv_bfloat162*)tmp;
    cudaGetSymbolAddress(&tmp, g_hop2l); p2l = (__nv_bfloat162*)tmp;
    cudaGetSymbolAddress(&tmp, g_hop3h); p3h = (__nv_bfloat162*)tmp;
    cudaGetSymbolAddress(&tmp, g_hop3l); p3l = (__nv_bfloat162*)tmp;
    cudaGetSymbolAddress(&tmp, g_h1h);   h1h = (__nv_bfloat162*)tmp;
    cudaGetSymbolAddress(&tmp, g_h1l);   h1l = (__nv_bfloat162*)tmp;
    cudaGetSymbolAddress(&tmp, g_h2h);   h2h = (__nv_bfloat162*)tmp;
    cudaGetSymbolAddress(&tmp, g_h2l);   h2l = (__nv_bfloat162*)tmp;
    cudaGetSymbolAddress(&tmp, g_w1h);   w1h = (__nv_bfloat16*)tmp;
    cudaGetSymbolAddress(&tmp, g_w1l);   w1l = (__nv_bfloat16*)tmp;
    cudaGetSymbolAddress(&tmp, g_w2h);   w2h = (__nv_bfloat16*)tmp;
    cudaGetSymbolAddress(&tmp, g_w2l);   w2l = (__nv_bfloat16*)tmp;

    cudaFuncSetAttribute(k_gemm_mma, cudaFuncAttributeMaxDynamicSharedMemorySize,
                         GEMM_SMEM);
    cudaFuncSetAttribute(k_cls_mma, cudaFuncAttributeMaxDynamicSharedMemorySize,
                         GEMM_SMEM);

    const int EB = (NE + 255) / 256;
    const int SB = (NN * 16 + 255) / 256;
    const int GB = (NN + 127) / 128;

    // ---- preprocessing (5 launches) ----
    k_wsplit<<<SCAN_NB, 256>>>(W1, W2, Wc);      // also zeroes g_cnt
    k_hist<<<EB, 256>>>(ei);
    k_scan1<<<SCAN_NB, 256>>>();
    k_scan23<<<SCAN_NB, 256>>>();
    k_fill<<<EB, 256>>>(ei);

    // ---- layer 1 ----
    k_spmm_f<<<SB, 256>>>((const float4*)x, p1h, p1l);
    k_spmm_s<<<SB, 256>>>(p1h, p1l, p2h, p2l);
    k_spmm_s<<<SB, 256>>>(p2h, p2l, p3h, p3l);
    k_gemm_mma<<<GB, 128, GEMM_SMEM>>>((const float4*)x, nullptr, nullptr,
                                       p1h, p1l, p2h, p2l, p3h, p3l,
                                       w1h, w1l, b1, h1h, h1l);

    // ---- layer 2 ----
    k_spmm_s<<<SB, 256>>>(h1h, h1l, p1h, p1l);
    k_spmm_s<<<SB, 256>>>(p1h, p1l, p2h, p2l);
    k_spmm_s<<<SB, 256>>>(p2h, p2l, p3h, p3l);
    k_gemm_mma<<<GB, 128, GEMM_SMEM>>>(nullptr, h1h, h1l,
                                       p1h, p1l, p2h, p2l, p3h, p3l,
                                       w2h, w2l, b2, h2h, h2l);

    // ---- classifier ----
    k_cls_mma<<<GB, 128, GEMM_SMEM>>>(h2h, h2l, bc, out);
}